// round 1
// baseline (speedup 1.0000x reference)
#include <cuda_runtime.h>
#include <cuda_bf16.h>

// Problem constants: nw_out is [N=4, C=19, H=512, W=1024] float32.
#define NCH   19
#define NBAT  4
#define HH    512
#define WW    1024
#define HWP   (HH * WW)          // 524288
#define NPIX  (NBAT * HWP)       // 2097152
#define IW_F  0.2f

// Scratch accumulators (no device allocation allowed -> __device__ globals).
__device__ float        g_sum[NCH];
__device__ unsigned int g_cnt[NCH];

__global__ void msiw_init_kernel() {
    int i = threadIdx.x;
    if (i < NCH) {
        g_sum[i] = 0.0f;
        g_cnt[i] = 0u;
    }
}

__global__ __launch_bounds__(256) void msiw_main_kernel(const float* __restrict__ x) {
    __shared__ float        s_sum[NCH];
    __shared__ unsigned int s_cnt[NCH];
    if (threadIdx.x < NCH) {
        s_sum[threadIdx.x] = 0.0f;
        s_cnt[threadIdx.x] = 0u;
    }
    __syncthreads();

    const int stride = gridDim.x * blockDim.x;
    for (int p = blockIdx.x * blockDim.x + threadIdx.x; p < NPIX; p += stride) {
        const int n  = p / HWP;             // batch index
        const int hw = p - n * HWP;         // position within image
        const float* base = x + (size_t)n * (NCH * HWP) + hw;

        // Load all 19 channel values (each load: 32 consecutive lanes ->
        // 128B coalesced transaction; full unroll -> 19-deep MLP).
        float v[NCH];
#pragma unroll
        for (int c = 0; c < NCH; c++) {
            v[c] = base[(size_t)c * HWP];
        }

        // argmax (first-max semantics like jnp.argmax: strict >)
        float m = v[0];
        int   idx = 0;
#pragma unroll
        for (int c = 1; c < NCH; c++) {
            if (v[c] > m) { m = v[c]; idx = c; }
        }

        // r = sum_c softmax(v)_c^2 = s2 / s1^2 (max-shifted for stability)
        float s1 = 0.0f, s2 = 0.0f;
#pragma unroll
        for (int c = 0; c < NCH; c++) {
            float e = __expf(v[c] - m);
            s1 += e;
            s2 = fmaf(e, e, s2);
        }
        float r = __fdividef(s2, s1 * s1);

        atomicAdd(&s_sum[idx], r);
        atomicAdd(&s_cnt[idx], 1u);
    }

    __syncthreads();
    if (threadIdx.x < NCH) {
        atomicAdd(&g_sum[threadIdx.x], s_sum[threadIdx.x]);
        atomicAdd(&g_cnt[threadIdx.x], s_cnt[threadIdx.x]);
    }
}

__global__ void msiw_finalize_kernel(float* __restrict__ out) {
    // single warp
    int c = threadIdx.x;
    float partial = 0.0f;
    if (c < NCH) {
        float cnt   = (float)g_cnt[c];
        float scale = powf((float)NPIX, 1.0f - IW_F);       // Np^0.8
        float den   = fmaxf(powf(cnt, IW_F) * scale, 1.0f); // max(hist^0.2 * Np^0.8, 1)
        partial = g_sum[c] / den;
    }
#pragma unroll
    for (int o = 16; o > 0; o >>= 1)
        partial += __shfl_down_sync(0xffffffffu, partial, o);
    if (c == 0)
        out[0] = -partial / (float)(NBAT * NCH);
}

extern "C" void kernel_launch(void* const* d_in, const int* in_sizes, int n_in,
                              void* d_out, int out_size) {
    (void)in_sizes; (void)n_in; (void)out_size;
    const float* x = (const float*)d_in[0];
    float* out = (float*)d_out;

    msiw_init_kernel<<<1, 32>>>();
    // 1024 blocks x 256 threads: each thread handles exactly 8 pixels
    // via the grid-stride loop (stride = 262144, keeps coalescing).
    msiw_main_kernel<<<1024, 256>>>(x);
    msiw_finalize_kernel<<<1, 32>>>(out);
}